// round 7
// baseline (speedup 1.0000x reference)
#include <cuda_runtime.h>
#include <stdint.h>

#define N_USERS 200000
#define N_ITEMS 100000
#define N_NODES 300000
#define N_EDGES 4800000
#define EMB 64
#define BATCH 4096
#define N_SEL 8192
#define CAP 128
#define NWORDS ((N_NODES + 31) / 32)   // 9375 words = 37.5KB

#define GRIDN 148
#define TPB 512
#define NTHREADS (GRIDN * TPB)
#define NWARPS (NTHREADS / 32)

// Scratch (device globals; zero-initialized at module load)
__device__ unsigned g_bits[NWORDS];
__device__ int      g_slot[N_NODES];      // node -> slot+1, 0 = unset
__device__ int      g_cnt[N_SEL];
__device__ uint2    g_list[N_SEL * CAP];
__device__ unsigned g_bar;                // grid barrier arrive count
__device__ unsigned g_gen;                // grid barrier generation

// Software grid barrier. Safe because grid == 148 blocks, 1 per SM,
// all co-resident from launch. g_gen monotonically grows across launches.
__device__ __forceinline__ void gridbar() {
    __syncthreads();
    if (threadIdx.x == 0) {
        __threadfence();
        unsigned gen = atomicAdd(&g_gen, 0u);
        if (atomicAdd(&g_bar, 1u) == GRIDN - 1u) {
            g_bar = 0u;
            __threadfence();
            atomicAdd(&g_gen, 1u);
        } else {
            while (atomicAdd(&g_gen, 0u) == gen) { }
            __threadfence();
        }
    }
    __syncthreads();
}

__global__ void __launch_bounds__(TPB, 1)
k_fused(const int*   __restrict__ adj_row,
        const int*   __restrict__ adj_col,
        const float* __restrict__ adj_vals,
        const float* __restrict__ user_emb,
        const float* __restrict__ item_emb,
        const int*   __restrict__ user_id,
        const int*   __restrict__ item_id,
        float*       __restrict__ out) {
    __shared__ unsigned s_bits[NWORDS];
    int tid = blockIdx.x * TPB + threadIdx.x;
    int lane = threadIdx.x & 31;

    // ---- Phase 0: clear this batch's touched state ----
    if (tid < N_SEL) {
        int node = (tid < BATCH) ? user_id[tid] : N_USERS + item_id[tid - BATCH];
        g_slot[node] = 0;
        atomicAnd(&g_bits[node >> 5], ~(1u << (node & 31)));
        g_cnt[tid] = 0;
    }
    gridbar();

    // ---- Phase 1: claim slots (any winner; duplicates indirect later) ----
    if (tid < N_SEL) {
        int node = (tid < BATCH) ? user_id[tid] : N_USERS + item_id[tid - BATCH];
        atomicOr(&g_bits[node >> 5], 1u << (node & 31));
        atomicCAS(&g_slot[node], 0, tid + 1);
    }
    gridbar();

    // ---- Phase 2: edge scan with smem bitmap, compact to per-slot lists ----
    for (int w = threadIdx.x; w < NWORDS; w += TPB)
        s_bits[w] = g_bits[w];
    __syncthreads();

    {
        const int4* row4 = (const int4*)adj_row;
        const int nchunks = N_EDGES / 4;
        for (int i = tid; i < nchunks; i += NTHREADS) {
            int4 r = row4[i];
            int e = i * 4;
#pragma unroll
            for (int k = 0; k < 4; k++) {
                int row = (k == 0) ? r.x : (k == 1) ? r.y : (k == 2) ? r.z : r.w;
                unsigned w = s_bits[row >> 5];
                if ((w >> (row & 31)) & 1u) {
                    int s = g_slot[row] - 1;
                    int pos = atomicAdd(&g_cnt[s], 1);
                    if (pos < CAP)
                        g_list[s * CAP + pos] =
                            make_uint2((unsigned)adj_col[e + k],
                                       __float_as_uint(adj_vals[e + k]));
                }
            }
        }
    }
    gridbar();

    // ---- Phase 3: accumulate, one warp per slot (grid-stride) ----
    int wid = tid >> 5;
    for (int s = wid; s < N_SEL; s += NWARPS) {
        int node = (s < BATCH) ? user_id[s] : N_USERS + item_id[s - BATCH];
        const float* xp = (node < N_USERS)
            ? user_emb + (size_t)node * EMB
            : item_emb + (size_t)(node - N_USERS) * EMB;
        float2 x2 = ((const float2*)xp)[lane];
        float ax = 2.0f * x2.x;
        float ay = 2.0f * x2.y;

        int w = g_slot[node] - 1;        // winner slot for this node
        int n = g_cnt[w];
        if (n > CAP) n = CAP;

        for (int base = 0; base < n; base += 32) {
            uint2 ent = make_uint2(0u, 0u);
            if (base + lane < n) ent = g_list[w * CAP + base + lane];
            int m = n - base;
            if (m > 32) m = 32;

            int k = 0;
            for (; k + 4 <= m; k += 4) {   // unpredicated 4-edge groups
                float  vv[4];
                float2 rr[4];
#pragma unroll
                for (int j = 0; j < 4; j++) {
                    int col = __shfl_sync(0xffffffffu, (int)ent.x, k + j);
                    vv[j] = __uint_as_float(
                        __shfl_sync(0xffffffffu, ent.y, k + j));
                    const float2* cp2 = (col < N_USERS)
                        ? (const float2*)(user_emb + (size_t)col * EMB)
                        : (const float2*)(item_emb +
                                          (size_t)(col - N_USERS) * EMB);
                    rr[j] = cp2[lane];      // 4 independent 256B loads
                }
#pragma unroll
                for (int j = 0; j < 4; j++) {
                    ax = fmaf(vv[j], rr[j].x, ax);
                    ay = fmaf(vv[j], rr[j].y, ay);
                }
            }
            for (; k < m; k++) {           // scalar tail
                int   col = __shfl_sync(0xffffffffu, (int)ent.x, k);
                float val = __uint_as_float(
                    __shfl_sync(0xffffffffu, ent.y, k));
                const float2* cp2 = (col < N_USERS)
                    ? (const float2*)(user_emb + (size_t)col * EMB)
                    : (const float2*)(item_emb +
                                      (size_t)(col - N_USERS) * EMB);
                float2 r = cp2[lane];
                ax = fmaf(val, r.x, ax);
                ay = fmaf(val, r.y, ay);
            }
        }
        ((float2*)out)[(size_t)s * 32 + lane] = make_float2(ax, ay);
    }
}

extern "C" void kernel_launch(void* const* d_in, const int* in_sizes, int n_in,
                              void* d_out, int out_size) {
    const float* user_emb = (const float*)d_in[0];
    const float* item_emb = (const float*)d_in[1];
    const int*   adj_row  = (const int*)d_in[2];
    const int*   adj_col  = (const int*)d_in[3];
    const float* adj_vals = (const float*)d_in[4];
    const int*   user_id  = (const int*)d_in[5];
    const int*   item_id  = (const int*)d_in[6];
    float*       out      = (float*)d_out;

    k_fused<<<GRIDN, TPB>>>(adj_row, adj_col, adj_vals,
                            user_emb, item_emb, user_id, item_id, out);
}

// round 9
// speedup vs baseline: 2.1847x; 2.1847x over previous
#include <cuda_runtime.h>
#include <stdint.h>

#define N_USERS 200000
#define N_ITEMS 100000
#define N_NODES 300000
#define N_EDGES 4800000
#define EMB 64
#define BATCH 4096
#define N_SEL 8192
#define CAP 128
#define NWORDS ((N_NODES + 31) / 32)

// Scratch (device globals; zero-initialized at module load)
__device__ unsigned           g_bits[NWORDS];     // batch membership bitmap
__device__ unsigned long long g_slotv[N_NODES];   // (gen<<13)|slot, gen-tagged
__device__ int                g_cnt[N_SEL];
__device__ uint2              g_list[N_SEL * CAP];
__device__ unsigned long long g_gen;              // completed-launch counter

// K1: claim slots with generation tags (no clearing needed) + zero counters.
// Winner among duplicate nodes = max slot id (deterministic).
__global__ void k_claim(const int* __restrict__ user_id,
                        const int* __restrict__ item_id) {
    int b = blockIdx.x * blockDim.x + threadIdx.x;
    if (b >= N_SEL) return;
    g_cnt[b] = 0;
    int node = (b < BATCH) ? user_id[b] : N_USERS + item_id[b - BATCH];
    unsigned long long tag = ((g_gen + 1ULL) << 13) | (unsigned long long)b;
    atomicOr(&g_bits[node >> 5], 1u << (node & 31));
    atomicMax(&g_slotv[node], tag);
}

// K2: coalesced edge scan (int4), L1-cached global bitmap filter,
// compact selected edges into per-slot lists. (Proven R2 shape.)
__global__ void k_scan(const int*   __restrict__ adj_row,
                       const int*   __restrict__ adj_col,
                       const float* __restrict__ adj_vals) {
    int i = blockIdx.x * blockDim.x + threadIdx.x;   // 4 edges per thread
    if (i >= N_EDGES / 4) return;
    int4 r = ((const int4*)adj_row)[i];
    int e = i * 4;
#pragma unroll
    for (int k = 0; k < 4; k++) {
        int row = (k == 0) ? r.x : (k == 1) ? r.y : (k == 2) ? r.z : r.w;
        unsigned w = g_bits[row >> 5];
        if ((w >> (row & 31)) & 1u) {
            // bit set => claimed THIS launch => tag is current
            int s = (int)(g_slotv[row] & 8191ULL);
            int pos = atomicAdd(&g_cnt[s], 1);
            if (pos < CAP)
                g_list[s * CAP + pos] =
                    make_uint2((unsigned)adj_col[e + k],
                               __float_as_uint(adj_vals[e + k]));
        }
    }
}

// K3: one warp per slot, winner indirection, float2 loads, 4-edge MLP
// groups (proven R4 body). Tail: clear this node's bit; slot 0 bumps gen.
__global__ void k_acc(const int*   __restrict__ user_id,
                      const int*   __restrict__ item_id,
                      const float* __restrict__ user_emb,
                      const float* __restrict__ item_emb,
                      float*       __restrict__ out) {
    int s = blockIdx.x * (blockDim.x >> 5) + (threadIdx.x >> 5);
    int lane = threadIdx.x & 31;
    if (s >= N_SEL) return;

    int node = (s < BATCH) ? user_id[s] : N_USERS + item_id[s - BATCH];
    const float* xp = (node < N_USERS)
        ? user_emb + (size_t)node * EMB
        : item_emb + (size_t)(node - N_USERS) * EMB;
    float2 x2 = ((const float2*)xp)[lane];
    float ax = 2.0f * x2.x;
    float ay = 2.0f * x2.y;

    int w = (int)(g_slotv[node] & 8191ULL);   // winner slot for this node
    int n = g_cnt[w];
    if (n > CAP) n = CAP;

    for (int base = 0; base < n; base += 32) {
        uint2 ent = make_uint2(0u, 0u);
        if (base + lane < n) ent = g_list[w * CAP + base + lane];
        int m = n - base;
        if (m > 32) m = 32;

        int k = 0;
        for (; k + 4 <= m; k += 4) {          // unpredicated 4-edge groups
            float  vv[4];
            float2 rr[4];
#pragma unroll
            for (int j = 0; j < 4; j++) {
                int col = __shfl_sync(0xffffffffu, (int)ent.x, k + j);
                vv[j] = __uint_as_float(
                    __shfl_sync(0xffffffffu, ent.y, k + j));
                const float2* cp2 = (col < N_USERS)
                    ? (const float2*)(user_emb + (size_t)col * EMB)
                    : (const float2*)(item_emb + (size_t)(col - N_USERS) * EMB);
                rr[j] = cp2[lane];             // 4 independent 256B loads
            }
#pragma unroll
            for (int j = 0; j < 4; j++) {
                ax = fmaf(vv[j], rr[j].x, ax);
                ay = fmaf(vv[j], rr[j].y, ay);
            }
        }
        for (; k < m; k++) {                   // scalar tail
            int   col = __shfl_sync(0xffffffffu, (int)ent.x, k);
            float val = __uint_as_float(__shfl_sync(0xffffffffu, ent.y, k));
            const float2* cp2 = (col < N_USERS)
                ? (const float2*)(user_emb + (size_t)col * EMB)
                : (const float2*)(item_emb + (size_t)(col - N_USERS) * EMB);
            float2 r = cp2[lane];
            ax = fmaf(val, r.x, ax);
            ay = fmaf(val, r.y, ay);
        }
    }
    ((float2*)out)[(size_t)s * 32 + lane] = make_float2(ax, ay);

    // cleanup for next replay: clear this node's bit (idempotent)
    if (lane == 0) {
        atomicAnd(&g_bits[node >> 5], ~(1u << (node & 31)));
        if (s == 0) atomicAdd(&g_gen, 1ULL);   // next launch uses gen+1
    }
}

extern "C" void kernel_launch(void* const* d_in, const int* in_sizes, int n_in,
                              void* d_out, int out_size) {
    const float* user_emb = (const float*)d_in[0];
    const float* item_emb = (const float*)d_in[1];
    const int*   adj_row  = (const int*)d_in[2];
    const int*   adj_col  = (const int*)d_in[3];
    const float* adj_vals = (const float*)d_in[4];
    const int*   user_id  = (const int*)d_in[5];
    const int*   item_id  = (const int*)d_in[6];
    float*       out      = (float*)d_out;

    const int T = 256;
    k_claim<<<(N_SEL + T - 1) / T, T>>>(user_id, item_id);
    k_scan <<<(N_EDGES / 4 + T - 1) / T, T>>>(adj_row, adj_col, adj_vals);
    k_acc  <<<N_SEL / (T / 32), T>>>(user_id, item_id, user_emb, item_emb, out);
}